// round 11
// baseline (speedup 1.0000x reference)
#include <cuda_runtime.h>
#include <cuda_bf16.h>

// FSRCNN: BS=1024, D=56, S=12, H=W=32 -> out 3x64x64
__device__ float g_h5[1024 * 12 * 1024];   // after b4 + prelu(b5_a)
__device__ float g_cpack[5064];            // staging: head constants

// constant-bank image: [0:4256) wh padded [oc][76], [4256:4928) w0t [oc][12],
// [4928:4984) hb, [4984:5040) ha, [5040:5052) b0b, [5052:5064) b0a
__constant__ __align__(16) float c_head[5064];

typedef unsigned long long ull;
__device__ __forceinline__ ull pk2(float lo, float hi) {
    ull r; asm("mov.b64 %0,{%1,%2};" : "=l"(r) : "f"(lo), "f"(hi)); return r;
}
__device__ __forceinline__ float2 upk2(ull v) {
    float2 o; asm("mov.b64 {%0,%1},%2;" : "=f"(o.x), "=f"(o.y) : "l"(v)); return o;
}
__device__ __forceinline__ ull ffma2(ull a, ull b, ull c) {
    ull d; asm("fma.rn.f32x2 %0,%1,%2,%3;" : "=l"(d) : "l"(a), "l"(b), "l"(c)); return d;
}

// ---------------------------------------------------------------------------
// Prep: pack head weights (padded/transposed) into g_cpack for the const copy.
// ---------------------------------------------------------------------------
__global__ __launch_bounds__(256) void k_prep(
    const float* __restrict__ head_w, const float* __restrict__ head_b,
    const float* __restrict__ head_a,
    const float* __restrict__ b0_w, const float* __restrict__ b0_b,
    const float* __restrict__ b0_a)
{
    const int i = blockIdx.x * 256 + threadIdx.x;
    if (i < 4256) {
        const int oc = i / 76, t = i % 76;
        g_cpack[i] = (t < 75) ? head_w[oc * 75 + t] : 0.f;
    } else if (i < 4928) {
        const int j = i - 4256;
        const int oc = j / 12, s = j % 12;
        g_cpack[i] = b0_w[s * 56 + oc];
    } else if (i < 4984) {
        g_cpack[i] = head_b[i - 4928];
    } else if (i < 5040) {
        g_cpack[i] = head_a[i - 4984];
    } else if (i < 5052) {
        g_cpack[i] = b0_b[i - 5040];
    } else if (i < 5064) {
        g_cpack[i] = b0_a[i - 5052];
    }
}

// ---------------------------------------------------------------------------
// Kernel 1 (merged): head 5x5 (3->56)+PReLU + b0 1x1 (56->12)+PReLU written
// DIRECTLY into the padded 34x34 smem buffer, then four 3x3 convs (12->12)
// with PReLU(b5_a) after the last. One block per image; h1 never hits HBM.
// ---------------------------------------------------------------------------
__global__ __launch_bounds__(256, 2) void k_hb(
    const float* __restrict__ x,
    const float* __restrict__ w1, const float* __restrict__ bb1,
    const float* __restrict__ w2, const float* __restrict__ bb2,
    const float* __restrict__ w3, const float* __restrict__ bb3,
    const float* __restrict__ w4, const float* __restrict__ bb4,
    const float* __restrict__ b5a)
{
    extern __shared__ float sm[];
    float* buf = sm;               // 12*1156 = 13872 (34x34 padded)
    float* ws  = sm + 13872;       // 4*1296 = 5184, [l][ic][tap9][oc12]
    float* bs  = sm + 19056;       // 48
    float* a5  = sm + 19104;       // 12
    float* xs  = sm + 19116;       // 3072
    // total 22188 floats = 88752 B

    const int tid = threadIdx.x;
    const int img = blockIdx.x;

    // ---- stage: input image, body weights, zero halo buffer ----
    const float* xim = x + img * 3072;
    for (int i = tid; i < 3072; i += 256) xs[i] = xim[i];

    const float* wl[4] = {w1, w2, w3, w4};
    const float* bl[4] = {bb1, bb2, bb3, bb4};
    for (int i = tid; i < 5184; i += 256) {
        const int l = i / 1296;
        const int r = i % 1296;
        const int ic = r / 108;
        const int r2 = r % 108;
        const int t = r2 / 12;
        const int oc = r2 % 12;
        ws[i] = wl[l][(oc * 12 + ic) * 9 + t];
    }
    if (tid < 48) bs[tid] = bl[tid / 12][tid % 12];
    if (tid < 12) a5[tid] = b5a[tid];
    for (int i = tid; i < 13872; i += 256) buf[i] = 0.f;
    __syncthreads();

    // ---- head phase: 4 pixels per thread, results -> buf interior ----
    for (int k = 0; k < 4; k++) {
        const int pix = k * 256 + tid;
        const int y = pix >> 5, x0 = pix & 31;

        float xr[76];
        xr[75] = 0.f;
#pragma unroll
        for (int ic = 0; ic < 3; ic++)
#pragma unroll
        for (int ky = 0; ky < 5; ky++) {
            const int yy = y + ky - 2;
#pragma unroll
            for (int kx = 0; kx < 5; kx++) {
                const int xx = x0 + kx - 2;
                const bool ok = (yy >= 0) & (yy < 32) & (xx >= 0) & (xx < 32);
                xr[ic * 25 + ky * 5 + kx] = ok ? xs[ic * 1024 + yy * 32 + xx] : 0.f;
            }
        }
        ull xp[38];
#pragma unroll
        for (int j = 0; j < 38; j++) xp[j] = pk2(xr[2 * j], xr[2 * j + 1]);

        ull acc2[6];
#pragma unroll
        for (int p = 0; p < 6; p++) acc2[p] = pk2(c_head[5040 + 2 * p], c_head[5041 + 2 * p]);

#pragma unroll 1
        for (int oc = 0; oc < 56; oc++) {
            const ulonglong2* wp = (const ulonglong2*)(c_head + oc * 76);
            ull aa0 = 0ULL, aa1 = 0ULL, aa2 = 0ULL, aa3 = 0ULL;
#pragma unroll
            for (int j = 0; j < 19; j += 2) {
                const ulonglong2 w = wp[j];
                aa0 = ffma2(xp[2 * j],     w.x, aa0);
                aa1 = ffma2(xp[2 * j + 1], w.y, aa1);
                if (j + 1 < 19) {
                    const ulonglong2 w2 = wp[j + 1];
                    aa2 = ffma2(xp[2 * j + 2], w2.x, aa2);
                    aa3 = ffma2(xp[2 * j + 3], w2.y, aa3);
                }
            }
            const float2 s0 = upk2(aa0), s1 = upk2(aa1);
            const float2 s2 = upk2(aa2), s3 = upk2(aa3);
            const float a = c_head[4928 + oc] + (((s0.x + s0.y) + (s1.x + s1.y)) +
                                                 ((s2.x + s2.y) + (s3.x + s3.y)));
            const float h = (a >= 0.f) ? a : c_head[4984 + oc] * a;
            const ull hh = pk2(h, h);
            const ulonglong2* q = (const ulonglong2*)(c_head + 4256 + oc * 12);
            const ulonglong2 q0 = q[0], q1 = q[1], q2 = q[2];
            acc2[0] = ffma2(hh, q0.x, acc2[0]);
            acc2[1] = ffma2(hh, q0.y, acc2[1]);
            acc2[2] = ffma2(hh, q1.x, acc2[2]);
            acc2[3] = ffma2(hh, q1.y, acc2[3]);
            acc2[4] = ffma2(hh, q2.x, acc2[4]);
            acc2[5] = ffma2(hh, q2.y, acc2[5]);
        }

        const int off = (y + 1) * 34 + (x0 + 1);
#pragma unroll
        for (int p = 0; p < 6; p++) {
            const float2 u = upk2(acc2[p]);
            float v0 = u.x, v1 = u.y;
            v0 = (v0 >= 0.f) ? v0 : c_head[5052 + 2 * p] * v0;
            v1 = (v1 >= 0.f) ? v1 : c_head[5053 + 2 * p] * v1;
            buf[(2 * p) * 1156 + off]     = v0;
            buf[(2 * p + 1) * 1156 + off] = v1;
        }
    }
    __syncthreads();

    // ---- body phase: four 3x3 convs in smem ----
    const int x2 = tid & 31;
    const int y0 = tid >> 5;
    int base[4];
#pragma unroll
    for (int k = 0; k < 4; k++) base[k] = (y0 + 8 * k + 1) * 34 + (x2 + 1);

    float* gout = g_h5 + img * 12288;

#pragma unroll 1
    for (int l = 0; l < 4; l++) {
        const float* wsl = ws + l * 1296;
        const float* bb = bs + l * 12;

        ull acc2[4][6];
#pragma unroll
        for (int k = 0; k < 4; k++)
#pragma unroll
            for (int p = 0; p < 6; p++) acc2[k][p] = pk2(bb[2 * p], bb[2 * p + 1]);

#pragma unroll 1
        for (int ic = 0; ic < 12; ic++) {
            const float* cb = buf + ic * 1156;
            float n[4][9];
#pragma unroll
            for (int k = 0; k < 4; k++) {
                const float* sp = cb + base[k];
                n[k][0] = sp[-35]; n[k][1] = sp[-34]; n[k][2] = sp[-33];
                n[k][3] = sp[-1];  n[k][4] = sp[0];   n[k][5] = sp[1];
                n[k][6] = sp[33];  n[k][7] = sp[34];  n[k][8] = sp[35];
            }
            const float* wic = wsl + ic * 108;
#pragma unroll
            for (int t = 0; t < 9; t++) {
                const ulonglong2* wt = (const ulonglong2*)(wic + t * 12);
                const ulonglong2 wA = wt[0];
                const ull wC = *(const ull*)(wic + t * 12 + 4);
                const ulonglong2 wB = *(const ulonglong2*)(wic + t * 12 + 6);
#pragma unroll
                for (int k = 0; k < 4; k++) {
                    const ull nb = pk2(n[k][t], n[k][t]);
                    acc2[k][0] = ffma2(nb, wA.x, acc2[k][0]);
                    acc2[k][1] = ffma2(nb, wA.y, acc2[k][1]);
                    acc2[k][2] = ffma2(nb, wC,   acc2[k][2]);
                    acc2[k][3] = ffma2(nb, wB.x, acc2[k][3]);
                    acc2[k][4] = ffma2(nb, wB.y, acc2[k][4]);
                    acc2[k][5] = ffma2(nb, *(const ull*)(wic + t * 12 + 10), acc2[k][5]);
                }
            }
        }

        if (l == 3) {
#pragma unroll
            for (int k = 0; k < 4; k++) {
                const int pix = k * 256 + tid;
#pragma unroll
                for (int p = 0; p < 6; p++) {
                    const float2 u = upk2(acc2[k][p]);
                    float v0 = u.x, v1 = u.y;
                    v0 = (v0 >= 0.f) ? v0 : a5[2 * p] * v0;
                    v1 = (v1 >= 0.f) ? v1 : a5[2 * p + 1] * v1;
                    gout[(2 * p) * 1024 + pix]     = v0;
                    gout[(2 * p + 1) * 1024 + pix] = v1;
                }
            }
        } else {
            __syncthreads();
#pragma unroll
            for (int k = 0; k < 4; k++)
#pragma unroll
                for (int p = 0; p < 6; p++) {
                    const float2 u = upk2(acc2[k][p]);
                    buf[(2 * p) * 1156 + base[k]]     = u.x;
                    buf[(2 * p + 1) * 1156 + base[k]] = u.y;
                }
            __syncthreads();
        }
    }
}

// ---------------------------------------------------------------------------
// Kernel 2 (fused): b6 1x1 (12->56) + PReLU in smem, then 9x9 stride-2
// transposed conv (56->3). Block = HALF image, 256 threads, 2 sites/thread,
// smem 111KB -> 2 CTAs/SM so chunk barriers of one CTA hide under the other
// CTA's FFMA2 stream. Phase A reads h5 directly from gmem.
// ---------------------------------------------------------------------------
__device__ __forceinline__ void cls2(const ulonglong2 ha, const ulonglong2 hb,
                                     const float* wt, int g, ull* P)
{
    const ulonglong2 w0 = *(const ulonglong2*)(wt + g);
    const ulonglong2 w1 = *(const ulonglong2*)(wt + 28 + g);
    const ulonglong2 w2 = *(const ulonglong2*)(wt + 56 + g);
    P[0] = ffma2(ha.x, w0.x, P[0]); P[0] = ffma2(ha.y, w0.y, P[0]);
    P[1] = ffma2(ha.x, w1.x, P[1]); P[1] = ffma2(ha.y, w1.y, P[1]);
    P[2] = ffma2(ha.x, w2.x, P[2]); P[2] = ffma2(ha.y, w2.y, P[2]);
    P[3] = ffma2(hb.x, w0.x, P[3]); P[3] = ffma2(hb.y, w0.y, P[3]);
    P[4] = ffma2(hb.x, w1.x, P[4]); P[4] = ffma2(hb.y, w1.y, P[4]);
    P[5] = ffma2(hb.x, w2.x, P[5]); P[5] = ffma2(hb.y, w2.y, P[5]);
}

__device__ __forceinline__ void accA(const float* hp, const float* wa, ull* A)
{
#pragma unroll
    for (int g = 0; g < 28; g += 4) {
        const ulonglong2 ha = *(const ulonglong2*)(hp + g);
        const ulonglong2 hb = *(const ulonglong2*)(hp + 448 + g);
        cls2(ha, hb, wa, g, A);
    }
}
__device__ __forceinline__ void accB(const float* hp, const float* wa, ull* A,
                                     const float* wb, ull* B)
{
#pragma unroll
    for (int g = 0; g < 28; g += 4) {
        const ulonglong2 ha = *(const ulonglong2*)(hp + g);
        const ulonglong2 hb = *(const ulonglong2*)(hp + 448 + g);
        cls2(ha, hb, wa, g, A);
        cls2(ha, hb, wb, g, B);
    }
}
__device__ __forceinline__ void accD(const float* hp,
                                     const float* w00, ull* A0,
                                     const float* w01, ull* A1,
                                     const float* w10, ull* A2,
                                     const float* w11, ull* A3)
{
#pragma unroll
    for (int g = 0; g < 28; g += 4) {
        const ulonglong2 ha = *(const ulonglong2*)(hp + g);
        const ulonglong2 hb = *(const ulonglong2*)(hp + 448 + g);
        cls2(ha, hb, w00, g, A0);
        cls2(ha, hb, w01, g, A1);
        cls2(ha, hb, w10, g, A2);
        cls2(ha, hb, w11, g, A3);
    }
}

__global__ __launch_bounds__(256, 2) void k_tail(
    const float* __restrict__ b6_w, const float* __restrict__ b6_b,
    const float* __restrict__ b6_a,
    const float* __restrict__ tail_w, const float* __restrict__ tail_b,
    float* __restrict__ out)
{
    extern __shared__ float sm[];
    float* h6c = sm;            // 720*28 = 20160   [p720][cl28], tile 20x36
    float* wtc = sm + 20160;    // 81*3*28 = 6804   [tap][oc][cl]
    float* b6w = sm + 26964;    // 672
    float* b6b = sm + 27636;    // 56
    float* b6a = sm + 27692;    // 56
    float* tb  = sm + 27748;    // 4
    // total 27752 floats = 111008 B

    const int tid = threadIdx.x;
    const int bid = blockIdx.x;
    const int img = bid >> 1;
    const int half = bid & 1;

    const float* h5g = g_h5 + img * 12288;

    for (int i = tid; i < 672; i += 256) b6w[i] = b6_w[i];
    if (tid < 56) { b6b[tid] = b6_b[tid]; b6a[tid] = b6_a[tid]; }
    if (tid < 3) tb[tid] = tail_b[tid];
    __syncthreads();

    const int sy = tid >> 4, sx = tid & 15;   // sites (sy,sx) and (sy,sx+16)

    ull acc[4][6];   // [parity][site0 oc0..2, site1 oc0..2]
#pragma unroll
    for (int p = 0; p < 4; p++)
#pragma unroll
        for (int o = 0; o < 6; o++) acc[p][o] = 0ULL;

#pragma unroll 1
    for (int cc = 0; cc < 2; cc++) {
        const int cb56 = cc * 28;
        if (cc) __syncthreads();    // protect wtc/h6c from previous readers

        // stage tail-weight chunk [tap81][oc3][cl28]
        for (int i = tid; i < 6804; i += 256) {
            const int tap = i / 84;
            const int rest = i % 84;
            const int oc = rest / 28;
            const int cl = rest % 28;
            wtc[i] = tail_w[(cb56 + cl) * 243 + oc * 81 + tap];
        }

        // phase A: expand 12 -> 28 channels for each of up to 3 tile pixels.
#pragma unroll 1
        for (int pp = 0; pp < 3; pp++) {
            const int p = tid + pp * 256;
            if (p >= 720) break;
            const int r = p / 36, s = p % 36;
            const int iy = half * 16 + r - 2, ix = s - 2;
            const bool valid = (iy >= 0) & (iy < 32) & (ix >= 0) & (ix < 32);
            const float* gp = h5g + iy * 32 + ix;
            float v[12];
#pragma unroll
            for (int c = 0; c < 12; c++)
                v[c] = valid ? __ldg(gp + c * 1024) : 0.f;

            float* hout = h6c + p * 28;
#pragma unroll 1
            for (int cl = 0; cl < 28; cl++) {
                const int c = cb56 + cl;
                const float4* wq = (const float4*)(b6w + c * 12);
                const float4 q0 = wq[0], q1 = wq[1], q2 = wq[2];
                float a = b6b[c];
                a = fmaf(v[0], q0.x, a);  a = fmaf(v[1], q0.y, a);
                a = fmaf(v[2], q0.z, a);  a = fmaf(v[3], q0.w, a);
                a = fmaf(v[4], q1.x, a);  a = fmaf(v[5], q1.y, a);
                a = fmaf(v[6], q1.z, a);  a = fmaf(v[7], q1.w, a);
                a = fmaf(v[8], q2.x, a);  a = fmaf(v[9], q2.y, a);
                a = fmaf(v[10], q2.z, a); a = fmaf(v[11], q2.w, a);
                a = (a >= 0.f) ? a : b6a[c] * a;
                hout[cl] = valid ? a : 0.f;
            }
        }
        __syncthreads();

        // phase B: transposed conv, all 4 parities x 2 sites per thread
        // dr=0 row (ky1 invalid)
        {
            const float* hr = h6c + (sy * 36 + sx) * 28;
            accA(hr, wtc + (8 * 9 + 8) * 84, acc[0]);
#pragma unroll 1
            for (int dc = 1; dc < 5; dc++) {
                const int kx0 = 8 - 2 * dc, kx1 = 9 - 2 * dc;
                accB(hr + dc * 28,
                     wtc + (8 * 9 + kx0) * 84, acc[0],
                     wtc + (8 * 9 + kx1) * 84, acc[1]);
            }
        }
#pragma unroll 1
        for (int dr = 1; dr < 5; dr++) {
            const int ky0 = 8 - 2 * dr, ky1 = 9 - 2 * dr;
            const float* hr = h6c + ((sy + dr) * 36 + sx) * 28;
            accB(hr,
                 wtc + (ky0 * 9 + 8) * 84, acc[0],
                 wtc + (ky1 * 9 + 8) * 84, acc[2]);
#pragma unroll 1
            for (int dc = 1; dc < 5; dc++) {
                const int kx0 = 8 - 2 * dc, kx1 = 9 - 2 * dc;
                accD(hr + dc * 28,
                     wtc + (ky0 * 9 + kx0) * 84, acc[0],
                     wtc + (ky0 * 9 + kx1) * 84, acc[1],
                     wtc + (ky1 * 9 + kx0) * 84, acc[2],
                     wtc + (ky1 * 9 + kx1) * 84, acc[3]);
            }
        }
    }

    float* o = out + img * 3 * 4096;
#pragma unroll
    for (int par = 0; par < 4; par++) {
        const int ry = par >> 1, rx = par & 1;
        const int oy = half * 32 + 2 * sy + ry;
#pragma unroll
        for (int s2 = 0; s2 < 2; s2++) {
            const int ox = 2 * (sx + 16 * s2) + rx;
#pragma unroll
            for (int oc = 0; oc < 3; oc++) {
                const float2 u = upk2(acc[par][s2 * 3 + oc]);
                o[oc * 4096 + oy * 64 + ox] = tb[oc] + (u.x + u.y);
            }
        }
    }
}

// ---------------------------------------------------------------------------
extern "C" void kernel_launch(void* const* d_in, const int* in_sizes, int n_in,
                              void* d_out, int out_size)
{
    const float* x      = (const float*)d_in[0];
    const float* head_w = (const float*)d_in[1];
    const float* head_b = (const float*)d_in[2];
    const float* head_a = (const float*)d_in[3];
    const float* b0_w   = (const float*)d_in[4];
    const float* b0_b   = (const float*)d_in[5];
    const float* b0_a   = (const float*)d_in[6];
    const float* b1_w   = (const float*)d_in[7];
    const float* b1_b   = (const float*)d_in[8];
    const float* b2_w   = (const float*)d_in[9];
    const float* b2_b   = (const float*)d_in[10];
    const float* b3_w   = (const float*)d_in[11];
    const float* b3_b   = (const float*)d_in[12];
    const float* b4_w   = (const float*)d_in[13];
    const float* b4_b   = (const float*)d_in[14];
    const float* b5_a   = (const float*)d_in[15];
    const float* b6_w   = (const float*)d_in[16];
    const float* b6_b   = (const float*)d_in[17];
    const float* b6_a   = (const float*)d_in[18];
    const float* tail_w = (const float*)d_in[19];
    const float* tail_b = (const float*)d_in[20];

    const int SMHB = 22188 * 4;   // k_hb dynamic smem (88.8 KB)
    const int SM4  = 27752 * 4;   // k_tail dynamic smem (111.0 KB)
    cudaFuncSetAttribute(k_hb,   cudaFuncAttributeMaxDynamicSharedMemorySize, SMHB);
    cudaFuncSetAttribute(k_tail, cudaFuncAttributeMaxDynamicSharedMemorySize, SM4);

    // stage head weights into constant bank (graph-capturable D2D copy)
    k_prep<<<20, 256>>>(head_w, head_b, head_a, b0_w, b0_b, b0_a);
    void* gsrc = nullptr;  cudaGetSymbolAddress(&gsrc, g_cpack);
    void* cdst = nullptr;  cudaGetSymbolAddress(&cdst, c_head);
    cudaMemcpyAsync(cdst, gsrc, 5064 * sizeof(float), cudaMemcpyDeviceToDevice, 0);

    k_hb<<<1024, 256, SMHB>>>(x, b1_w, b1_b, b2_w, b2_b, b3_w, b3_b, b4_w, b4_b, b5_a);
    k_tail<<<2048, 256, SM4>>>(b6_w, b6_b, b6_a, tail_w, tail_b, (float*)d_out);
}

// round 12
// speedup vs baseline: 1.0148x; 1.0148x over previous
#include <cuda_runtime.h>
#include <cuda_bf16.h>

// FSRCNN: BS=1024, D=56, S=12, H=W=32 -> out 3x64x64
__device__ float g_h5[1024 * 12 * 1024];   // after b4 + prelu(b5_a)
__device__ float g_cpack[5064];            // staging: head constants

// constant-bank image: [0:4256) wh padded [oc][76], [4256:4928) w0t [oc][12],
// [4928:4984) hb, [4984:5040) ha, [5040:5052) b0b, [5052:5064) b0a
__constant__ __align__(16) float c_head[5064];

typedef unsigned long long ull;
__device__ __forceinline__ ull pk2(float lo, float hi) {
    ull r; asm("mov.b64 %0,{%1,%2};" : "=l"(r) : "f"(lo), "f"(hi)); return r;
}
__device__ __forceinline__ float2 upk2(ull v) {
    float2 o; asm("mov.b64 {%0,%1},%2;" : "=f"(o.x), "=f"(o.y) : "l"(v)); return o;
}
__device__ __forceinline__ ull ffma2(ull a, ull b, ull c) {
    ull d; asm("fma.rn.f32x2 %0,%1,%2,%3;" : "=l"(d) : "l"(a), "l"(b), "l"(c)); return d;
}

// ---------------------------------------------------------------------------
// Prep: pack head weights (padded/transposed) into g_cpack for the const copy.
// ---------------------------------------------------------------------------
__global__ __launch_bounds__(256) void k_prep(
    const float* __restrict__ head_w, const float* __restrict__ head_b,
    const float* __restrict__ head_a,
    const float* __restrict__ b0_w, const float* __restrict__ b0_b,
    const float* __restrict__ b0_a)
{
    const int i = blockIdx.x * 256 + threadIdx.x;
    if (i < 4256) {
        const int oc = i / 76, t = i % 76;
        g_cpack[i] = (t < 75) ? head_w[oc * 75 + t] : 0.f;
    } else if (i < 4928) {
        const int j = i - 4256;
        const int oc = j / 12, s = j % 12;
        g_cpack[i] = b0_w[s * 56 + oc];
    } else if (i < 4984) {
        g_cpack[i] = head_b[i - 4928];
    } else if (i < 5040) {
        g_cpack[i] = head_a[i - 4984];
    } else if (i < 5052) {
        g_cpack[i] = b0_b[i - 5040];
    } else if (i < 5064) {
        g_cpack[i] = b0_a[i - 5052];
    }
}

// ---------------------------------------------------------------------------
// Kernel 1 (merged): head 5x5 (3->56)+PReLU + b0 1x1 (56->12)+PReLU written
// DIRECTLY into the padded 34x34 smem buffer, then four 3x3 convs (12->12)
// with PReLU(b5_a) after the last. One block per image; h1 never hits HBM.
// ---------------------------------------------------------------------------
__global__ __launch_bounds__(256, 2) void k_hb(
    const float* __restrict__ x,
    const float* __restrict__ w1, const float* __restrict__ bb1,
    const float* __restrict__ w2, const float* __restrict__ bb2,
    const float* __restrict__ w3, const float* __restrict__ bb3,
    const float* __restrict__ w4, const float* __restrict__ bb4,
    const float* __restrict__ b5a)
{
    extern __shared__ float sm[];
    float* buf = sm;               // 12*1156 = 13872 (34x34 padded)
    float* ws  = sm + 13872;       // 4*1296 = 5184, [l][ic][tap9][oc12]
    float* bs  = sm + 19056;       // 48
    float* a5  = sm + 19104;       // 12
    float* xs  = sm + 19116;       // 3072
    // total 22188 floats = 88752 B

    const int tid = threadIdx.x;
    const int img = blockIdx.x;

    // ---- stage: input image, body weights, zero halo buffer ----
    const float* xim = x + img * 3072;
    for (int i = tid; i < 3072; i += 256) xs[i] = xim[i];

    const float* wl[4] = {w1, w2, w3, w4};
    const float* bl[4] = {bb1, bb2, bb3, bb4};
    for (int i = tid; i < 5184; i += 256) {
        const int l = i / 1296;
        const int r = i % 1296;
        const int ic = r / 108;
        const int r2 = r % 108;
        const int t = r2 / 12;
        const int oc = r2 % 12;
        ws[i] = wl[l][(oc * 12 + ic) * 9 + t];
    }
    if (tid < 48) bs[tid] = bl[tid / 12][tid % 12];
    if (tid < 12) a5[tid] = b5a[tid];
    for (int i = tid; i < 13872; i += 256) buf[i] = 0.f;
    __syncthreads();

    // ---- head phase: 4 pixels per thread, results -> buf interior ----
    for (int k = 0; k < 4; k++) {
        const int pix = k * 256 + tid;
        const int y = pix >> 5, x0 = pix & 31;

        float xr[76];
        xr[75] = 0.f;
#pragma unroll
        for (int ic = 0; ic < 3; ic++)
#pragma unroll
        for (int ky = 0; ky < 5; ky++) {
            const int yy = y + ky - 2;
#pragma unroll
            for (int kx = 0; kx < 5; kx++) {
                const int xx = x0 + kx - 2;
                const bool ok = (yy >= 0) & (yy < 32) & (xx >= 0) & (xx < 32);
                xr[ic * 25 + ky * 5 + kx] = ok ? xs[ic * 1024 + yy * 32 + xx] : 0.f;
            }
        }
        ull xp[38];
#pragma unroll
        for (int j = 0; j < 38; j++) xp[j] = pk2(xr[2 * j], xr[2 * j + 1]);

        ull acc2[6];
#pragma unroll
        for (int p = 0; p < 6; p++) acc2[p] = pk2(c_head[5040 + 2 * p], c_head[5041 + 2 * p]);

#pragma unroll 1
        for (int oc = 0; oc < 56; oc++) {
            const ulonglong2* wp = (const ulonglong2*)(c_head + oc * 76);
            ull aa0 = 0ULL, aa1 = 0ULL, aa2 = 0ULL, aa3 = 0ULL;
#pragma unroll
            for (int j = 0; j < 19; j += 2) {
                const ulonglong2 w = wp[j];
                aa0 = ffma2(xp[2 * j],     w.x, aa0);
                aa1 = ffma2(xp[2 * j + 1], w.y, aa1);
                if (j + 1 < 19) {
                    const ulonglong2 w2 = wp[j + 1];
                    aa2 = ffma2(xp[2 * j + 2], w2.x, aa2);
                    aa3 = ffma2(xp[2 * j + 3], w2.y, aa3);
                }
            }
            const float2 s0 = upk2(aa0), s1 = upk2(aa1);
            const float2 s2 = upk2(aa2), s3 = upk2(aa3);
            const float a = c_head[4928 + oc] + (((s0.x + s0.y) + (s1.x + s1.y)) +
                                                 ((s2.x + s2.y) + (s3.x + s3.y)));
            const float h = (a >= 0.f) ? a : c_head[4984 + oc] * a;
            const ull hh = pk2(h, h);
            const ulonglong2* q = (const ulonglong2*)(c_head + 4256 + oc * 12);
            const ulonglong2 q0 = q[0], q1 = q[1], q2 = q[2];
            acc2[0] = ffma2(hh, q0.x, acc2[0]);
            acc2[1] = ffma2(hh, q0.y, acc2[1]);
            acc2[2] = ffma2(hh, q1.x, acc2[2]);
            acc2[3] = ffma2(hh, q1.y, acc2[3]);
            acc2[4] = ffma2(hh, q2.x, acc2[4]);
            acc2[5] = ffma2(hh, q2.y, acc2[5]);
        }

        const int off = (y + 1) * 34 + (x0 + 1);
#pragma unroll
        for (int p = 0; p < 6; p++) {
            const float2 u = upk2(acc2[p]);
            float v0 = u.x, v1 = u.y;
            v0 = (v0 >= 0.f) ? v0 : c_head[5052 + 2 * p] * v0;
            v1 = (v1 >= 0.f) ? v1 : c_head[5053 + 2 * p] * v1;
            buf[(2 * p) * 1156 + off]     = v0;
            buf[(2 * p + 1) * 1156 + off] = v1;
        }
    }
    __syncthreads();

    // ---- body phase: four 3x3 convs in smem ----
    const int x2 = tid & 31;
    const int y0 = tid >> 5;
    int base[4];
#pragma unroll
    for (int k = 0; k < 4; k++) base[k] = (y0 + 8 * k + 1) * 34 + (x2 + 1);

    float* gout = g_h5 + img * 12288;

#pragma unroll 1
    for (int l = 0; l < 4; l++) {
        const float* wsl = ws + l * 1296;
        const float* bb = bs + l * 12;

        ull acc2[4][6];
#pragma unroll
        for (int k = 0; k < 4; k++)
#pragma unroll
            for (int p = 0; p < 6; p++) acc2[k][p] = pk2(bb[2 * p], bb[2 * p + 1]);

#pragma unroll 1
        for (int ic = 0; ic < 12; ic++) {
            const float* cb = buf + ic * 1156;
            float n[4][9];
#pragma unroll
            for (int k = 0; k < 4; k++) {
                const float* sp = cb + base[k];
                n[k][0] = sp[-35]; n[k][1] = sp[-34]; n[k][2] = sp[-33];
                n[k][3] = sp[-1];  n[k][4] = sp[0];   n[k][5] = sp[1];
                n[k][6] = sp[33];  n[k][7] = sp[34];  n[k][8] = sp[35];
            }
            const float* wic = wsl + ic * 108;
#pragma unroll
            for (int t = 0; t < 9; t++) {
                const ulonglong2* wt = (const ulonglong2*)(wic + t * 12);
                const ulonglong2 wA = wt[0];
                const ull wC = *(const ull*)(wic + t * 12 + 4);
                const ulonglong2 wB = *(const ulonglong2*)(wic + t * 12 + 6);
#pragma unroll
                for (int k = 0; k < 4; k++) {
                    const ull nb = pk2(n[k][t], n[k][t]);
                    acc2[k][0] = ffma2(nb, wA.x, acc2[k][0]);
                    acc2[k][1] = ffma2(nb, wA.y, acc2[k][1]);
                    acc2[k][2] = ffma2(nb, wC,   acc2[k][2]);
                    acc2[k][3] = ffma2(nb, wB.x, acc2[k][3]);
                    acc2[k][4] = ffma2(nb, wB.y, acc2[k][4]);
                    acc2[k][5] = ffma2(nb, *(const ull*)(wic + t * 12 + 10), acc2[k][5]);
                }
            }
        }

        if (l == 3) {
#pragma unroll
            for (int k = 0; k < 4; k++) {
                const int pix = k * 256 + tid;
#pragma unroll
                for (int p = 0; p < 6; p++) {
                    const float2 u = upk2(acc2[k][p]);
                    float v0 = u.x, v1 = u.y;
                    v0 = (v0 >= 0.f) ? v0 : a5[2 * p] * v0;
                    v1 = (v1 >= 0.f) ? v1 : a5[2 * p + 1] * v1;
                    gout[(2 * p) * 1024 + pix]     = v0;
                    gout[(2 * p + 1) * 1024 + pix] = v1;
                }
            }
        } else {
            __syncthreads();
#pragma unroll
            for (int k = 0; k < 4; k++)
#pragma unroll
                for (int p = 0; p < 6; p++) {
                    const float2 u = upk2(acc2[k][p]);
                    buf[(2 * p) * 1156 + base[k]]     = u.x;
                    buf[(2 * p + 1) * 1156 + base[k]] = u.y;
                }
            __syncthreads();
        }
    }
}

// ---------------------------------------------------------------------------
// Kernel 2 (fused, R10/R8 tail): b6 1x1 (12->56) + PReLU in smem, then 9x9
// stride-2 transposed conv (56->3). Whole image / 512 threads / 2 sites per
// thread; channel chunks of 28; weights staged in smem per chunk.
// ---------------------------------------------------------------------------
__device__ __forceinline__ void cls2(const ulonglong2 ha, const ulonglong2 hb,
                                     const float* wt, int g, ull* P)
{
    const ulonglong2 w0 = *(const ulonglong2*)(wt + g);
    const ulonglong2 w1 = *(const ulonglong2*)(wt + 28 + g);
    const ulonglong2 w2 = *(const ulonglong2*)(wt + 56 + g);
    P[0] = ffma2(ha.x, w0.x, P[0]); P[0] = ffma2(ha.y, w0.y, P[0]);
    P[1] = ffma2(ha.x, w1.x, P[1]); P[1] = ffma2(ha.y, w1.y, P[1]);
    P[2] = ffma2(ha.x, w2.x, P[2]); P[2] = ffma2(ha.y, w2.y, P[2]);
    P[3] = ffma2(hb.x, w0.x, P[3]); P[3] = ffma2(hb.y, w0.y, P[3]);
    P[4] = ffma2(hb.x, w1.x, P[4]); P[4] = ffma2(hb.y, w1.y, P[4]);
    P[5] = ffma2(hb.x, w2.x, P[5]); P[5] = ffma2(hb.y, w2.y, P[5]);
}

__device__ __forceinline__ void accA(const float* hp, const float* wa, ull* A)
{
#pragma unroll
    for (int g = 0; g < 28; g += 4) {
        const ulonglong2 ha = *(const ulonglong2*)(hp + g);
        const ulonglong2 hb = *(const ulonglong2*)(hp + 448 + g);
        cls2(ha, hb, wa, g, A);
    }
}
__device__ __forceinline__ void accB(const float* hp, const float* wa, ull* A,
                                     const float* wb, ull* B)
{
#pragma unroll
    for (int g = 0; g < 28; g += 4) {
        const ulonglong2 ha = *(const ulonglong2*)(hp + g);
        const ulonglong2 hb = *(const ulonglong2*)(hp + 448 + g);
        cls2(ha, hb, wa, g, A);
        cls2(ha, hb, wb, g, B);
    }
}
__device__ __forceinline__ void accD(const float* hp,
                                     const float* w00, ull* A0,
                                     const float* w01, ull* A1,
                                     const float* w10, ull* A2,
                                     const float* w11, ull* A3)
{
#pragma unroll
    for (int g = 0; g < 28; g += 4) {
        const ulonglong2 ha = *(const ulonglong2*)(hp + g);
        const ulonglong2 hb = *(const ulonglong2*)(hp + 448 + g);
        cls2(ha, hb, w00, g, A0);
        cls2(ha, hb, w01, g, A1);
        cls2(ha, hb, w10, g, A2);
        cls2(ha, hb, w11, g, A3);
    }
}

__global__ __launch_bounds__(512, 1) void k_tail(
    const float* __restrict__ b6_w, const float* __restrict__ b6_b,
    const float* __restrict__ b6_a,
    const float* __restrict__ tail_w, const float* __restrict__ tail_b,
    float* __restrict__ out)
{
    extern __shared__ float sm[];
    float* h6c = sm;            // 1296*28 = 36288  [p1296][cl28], tile 36x36
    float* wtc = sm + 36288;    // 81*3*28 = 6804   [tap][oc][cl]
    float* b6w = sm + 43092;    // 672
    float* b6b = sm + 43764;    // 56
    float* b6a = sm + 43820;    // 56
    float* tb  = sm + 43876;    // 4
    // total 43880 floats = 175520 B

    const int tid = threadIdx.x;
    const int img = blockIdx.x;

    const float* h5g = g_h5 + img * 12288;

    for (int i = tid; i < 672; i += 512) b6w[i] = b6_w[i];
    if (tid < 56) { b6b[tid] = b6_b[tid]; b6a[tid] = b6_a[tid]; }
    if (tid < 3) tb[tid] = tail_b[tid];
    __syncthreads();

    const int sy = tid >> 4, sx = tid & 15;   // sites (sy,sx) and (sy,sx+16)

    ull acc[4][6];   // [parity][site0 oc0..2, site1 oc0..2]
#pragma unroll
    for (int p = 0; p < 4; p++)
#pragma unroll
        for (int o = 0; o < 6; o++) acc[p][o] = 0ULL;

#pragma unroll 1
    for (int cc = 0; cc < 2; cc++) {
        const int cb56 = cc * 28;
        if (cc) __syncthreads();    // protect wtc/h6c from previous readers

        // stage tail-weight chunk [tap81][oc3][cl28]
        for (int i = tid; i < 6804; i += 512) {
            const int tap = i / 84;
            const int rest = i % 84;
            const int oc = rest / 28;
            const int cl = rest % 28;
            wtc[i] = tail_w[(cb56 + cl) * 243 + oc * 81 + tap];
        }

        // phase A: expand 12 -> 28 channels for each of up to 3 tile pixels.
#pragma unroll 1
        for (int pp = 0; pp < 3; pp++) {
            const int p = tid + pp * 512;
            if (p >= 1296) break;
            const int r = p / 36, s = p % 36;
            const int iy = r - 2, ix = s - 2;
            const bool valid = (iy >= 0) & (iy < 32) & (ix >= 0) & (ix < 32);
            const float* gp = h5g + iy * 32 + ix;
            float v[12];
#pragma unroll
            for (int c = 0; c < 12; c++)
                v[c] = valid ? __ldg(gp + c * 1024) : 0.f;

            float* hout = h6c + p * 28;
#pragma unroll 1
            for (int cl = 0; cl < 28; cl++) {
                const int c = cb56 + cl;
                const float4* wq = (const float4*)(b6w + c * 12);
                const float4 q0 = wq[0], q1 = wq[1], q2 = wq[2];
                float a = b6b[c];
                a = fmaf(v[0], q0.x, a);  a = fmaf(v[1], q0.y, a);
                a = fmaf(v[2], q0.z, a);  a = fmaf(v[3], q0.w, a);
                a = fmaf(v[4], q1.x, a);  a = fmaf(v[5], q1.y, a);
                a = fmaf(v[6], q1.z, a);  a = fmaf(v[7], q1.w, a);
                a = fmaf(v[8], q2.x, a);  a = fmaf(v[9], q2.y, a);
                a = fmaf(v[10], q2.z, a); a = fmaf(v[11], q2.w, a);
                a = (a >= 0.f) ? a : b6a[c] * a;
                hout[cl] = valid ? a : 0.f;
            }
        }
        __syncthreads();

        // phase B: transposed conv, all 4 parities x 2 sites per thread
        // dr=0 row (ky1 invalid)
        {
            const float* hr = h6c + (sy * 36 + sx) * 28;
            accA(hr, wtc + (8 * 9 + 8) * 84, acc[0]);
#pragma unroll 1
            for (int dc = 1; dc < 5; dc++) {
                const int kx0 = 8 - 2 * dc, kx1 = 9 - 2 * dc;
                accB(hr + dc * 28,
                     wtc + (8 * 9 + kx0) * 84, acc[0],
                     wtc + (8 * 9 + kx1) * 84, acc[1]);
            }
        }
#pragma unroll 1
        for (int dr = 1; dr < 5; dr++) {
            const int ky0 = 8 - 2 * dr, ky1 = 9 - 2 * dr;
            const float* hr = h6c + ((sy + dr) * 36 + sx) * 28;
            accB(hr,
                 wtc + (ky0 * 9 + 8) * 84, acc[0],
                 wtc + (ky1 * 9 + 8) * 84, acc[2]);
#pragma unroll 1
            for (int dc = 1; dc < 5; dc++) {
                const int kx0 = 8 - 2 * dc, kx1 = 9 - 2 * dc;
                accD(hr + dc * 28,
                     wtc + (ky0 * 9 + kx0) * 84, acc[0],
                     wtc + (ky0 * 9 + kx1) * 84, acc[1],
                     wtc + (ky1 * 9 + kx0) * 84, acc[2],
                     wtc + (ky1 * 9 + kx1) * 84, acc[3]);
            }
        }
    }

    float* o = out + img * 3 * 4096;
#pragma unroll
    for (int par = 0; par < 4; par++) {
        const int ry = par >> 1, rx = par & 1;
        const int oy = 2 * sy + ry;
#pragma unroll
        for (int s2 = 0; s2 < 2; s2++) {
            const int ox = 2 * (sx + 16 * s2) + rx;
#pragma unroll
            for (int oc = 0; oc < 3; oc++) {
                const float2 u = upk2(acc[par][s2 * 3 + oc]);
                o[oc * 4096 + oy * 64 + ox] = tb[oc] + (u.x + u.y);
            }
        }
    }
}

// ---------------------------------------------------------------------------
extern "C" void kernel_launch(void* const* d_in, const int* in_sizes, int n_in,
                              void* d_out, int out_size)
{
    const float* x      = (const float*)d_in[0];
    const float* head_w = (const float*)d_in[1];
    const float* head_b = (const float*)d_in[2];
    const float* head_a = (const float*)d_in[3];
    const float* b0_w   = (const float*)d_in[4];
    const float* b0_b   = (const float*)d_in[5];
    const float* b0_a   = (const float*)d_in[6];
    const float* b1_w   = (const float*)d_in[7];
    const float* b1_b   = (const float*)d_in[8];
    const float* b2_w   = (const float*)d_in[9];
    const float* b2_b   = (const float*)d_in[10];
    const float* b3_w   = (const float*)d_in[11];
    const float* b3_b   = (const float*)d_in[12];
    const float* b4_w   = (const float*)d_in[13];
    const float* b4_b   = (const float*)d_in[14];
    const float* b5_a   = (const float*)d_in[15];
    const float* b6_w   = (const float*)d_in[16];
    const float* b6_b   = (const float*)d_in[17];
    const float* b6_a   = (const float*)d_in[18];
    const float* tail_w = (const float*)d_in[19];
    const float* tail_b = (const float*)d_in[20];

    const int SMHB = 22188 * 4;   // k_hb dynamic smem (88.8 KB)
    const int SM4  = 43880 * 4;   // k_tail dynamic smem (175.5 KB)
    cudaFuncSetAttribute(k_hb,   cudaFuncAttributeMaxDynamicSharedMemorySize, SMHB);
    cudaFuncSetAttribute(k_tail, cudaFuncAttributeMaxDynamicSharedMemorySize, SM4);

    // stage head weights into constant bank (graph-capturable D2D copy)
    k_prep<<<20, 256>>>(head_w, head_b, head_a, b0_w, b0_b, b0_a);
    void* gsrc = nullptr;  cudaGetSymbolAddress(&gsrc, g_cpack);
    void* cdst = nullptr;  cudaGetSymbolAddress(&cdst, c_head);
    cudaMemcpyAsync(cdst, gsrc, 5064 * sizeof(float), cudaMemcpyDeviceToDevice, 0);

    k_hb<<<1024, 256, SMHB>>>(x, b1_w, b1_b, b2_w, b2_b, b3_w, b3_b, b4_w, b4_b, b5_a);
    k_tail<<<1024, 512, SM4>>>(b6_w, b6_b, b6_a, tail_w, tail_b, (float*)d_out);
}

// round 13
// speedup vs baseline: 1.2986x; 1.2796x over previous
#include <cuda_runtime.h>
#include <cuda_bf16.h>

// FSRCNN: BS=1024, D=56, S=12, H=W=32 -> out 3x64x64
__device__ float g_h1[1024 * 12 * 1024];   // after b0 + prelu
__device__ float g_h5[1024 * 12 * 1024];   // after b4 + prelu(b5_a)
__device__ float g_cpack[5064];            // staging: head constants

// constant-bank image: [0:4256) wh padded [oc][76], [4256:4928) w0t [oc][12],
// [4928:4984) hb, [4984:5040) ha, [5040:5052) b0b, [5052:5064) b0a
__constant__ __align__(16) float c_head[5064];

typedef unsigned long long ull;
__device__ __forceinline__ ull pk2(float lo, float hi) {
    ull r; asm("mov.b64 %0,{%1,%2};" : "=l"(r) : "f"(lo), "f"(hi)); return r;
}
__device__ __forceinline__ float2 upk2(ull v) {
    float2 o; asm("mov.b64 {%0,%1},%2;" : "=f"(o.x), "=f"(o.y) : "l"(v)); return o;
}
__device__ __forceinline__ ull ffma2(ull a, ull b, ull c) {
    ull d; asm("fma.rn.f32x2 %0,%1,%2,%3;" : "=l"(d) : "l"(a), "l"(b), "l"(c)); return d;
}

// ---------------------------------------------------------------------------
// Prep: pack head weights (padded/transposed) into g_cpack for the const copy.
// ---------------------------------------------------------------------------
__global__ __launch_bounds__(256) void k_prep(
    const float* __restrict__ head_w, const float* __restrict__ head_b,
    const float* __restrict__ head_a,
    const float* __restrict__ b0_w, const float* __restrict__ b0_b,
    const float* __restrict__ b0_a)
{
    const int i = blockIdx.x * 256 + threadIdx.x;
    if (i < 4256) {
        const int oc = i / 76, t = i % 76;
        g_cpack[i] = (t < 75) ? head_w[oc * 75 + t] : 0.f;
    } else if (i < 4928) {
        const int j = i - 4256;
        const int oc = j / 12, s = j % 12;
        g_cpack[i] = b0_w[s * 56 + oc];
    } else if (i < 4984) {
        g_cpack[i] = head_b[i - 4928];
    } else if (i < 5040) {
        g_cpack[i] = head_a[i - 4984];
    } else if (i < 5052) {
        g_cpack[i] = b0_b[i - 5040];
    } else if (i < 5064) {
        g_cpack[i] = b0_a[i - 5052];
    }
}

// ---------------------------------------------------------------------------
// Kernel 1: head 5x5 conv (3->56, pad2) + PReLU + b0 1x1 (56->12) + PReLU
// Weights in the CONSTANT BANK; smem crossbar only serves x gathers.
// ---------------------------------------------------------------------------
__global__ __launch_bounds__(256) void k_head(const float* __restrict__ x)
{
    __shared__ float xs[3 * 1024];

    const int tid = threadIdx.x;
    const int img = blockIdx.x;

    const float* xim = x + img * 3072;
    for (int i = tid; i < 3072; i += 256) xs[i] = xim[i];
    __syncthreads();

    float* out = g_h1 + img * 12288;

    for (int k = 0; k < 4; k++) {
        const int pix = k * 256 + tid;
        const int y = pix >> 5, x0 = pix & 31;

        float xr[76];
        xr[75] = 0.f;
#pragma unroll
        for (int ic = 0; ic < 3; ic++)
#pragma unroll
        for (int ky = 0; ky < 5; ky++) {
            const int yy = y + ky - 2;
#pragma unroll
            for (int kx = 0; kx < 5; kx++) {
                const int xx = x0 + kx - 2;
                const bool ok = (yy >= 0) & (yy < 32) & (xx >= 0) & (xx < 32);
                xr[ic * 25 + ky * 5 + kx] = ok ? xs[ic * 1024 + yy * 32 + xx] : 0.f;
            }
        }
        ull xp[38];
#pragma unroll
        for (int j = 0; j < 38; j++) xp[j] = pk2(xr[2 * j], xr[2 * j + 1]);

        ull acc2[6];
#pragma unroll
        for (int p = 0; p < 6; p++) acc2[p] = pk2(c_head[5040 + 2 * p], c_head[5041 + 2 * p]);

#pragma unroll 2
        for (int oc = 0; oc < 56; oc++) {
            const ulonglong2* wp = (const ulonglong2*)(c_head + oc * 76);
            ull aa0 = 0ULL, aa1 = 0ULL, aa2 = 0ULL, aa3 = 0ULL;
#pragma unroll
            for (int j = 0; j < 19; j += 2) {
                const ulonglong2 w = wp[j];
                aa0 = ffma2(xp[2 * j],     w.x, aa0);
                aa1 = ffma2(xp[2 * j + 1], w.y, aa1);
                if (j + 1 < 19) {
                    const ulonglong2 w2 = wp[j + 1];
                    aa2 = ffma2(xp[2 * j + 2], w2.x, aa2);
                    aa3 = ffma2(xp[2 * j + 3], w2.y, aa3);
                }
            }
            const float2 s0 = upk2(aa0), s1 = upk2(aa1);
            const float2 s2 = upk2(aa2), s3 = upk2(aa3);
            const float a = c_head[4928 + oc] + (((s0.x + s0.y) + (s1.x + s1.y)) +
                                                 ((s2.x + s2.y) + (s3.x + s3.y)));
            const float h = (a >= 0.f) ? a : c_head[4984 + oc] * a;
            const ull hh = pk2(h, h);
            const ulonglong2* q = (const ulonglong2*)(c_head + 4256 + oc * 12);
            const ulonglong2 q0 = q[0], q1 = q[1], q2 = q[2];
            acc2[0] = ffma2(hh, q0.x, acc2[0]);
            acc2[1] = ffma2(hh, q0.y, acc2[1]);
            acc2[2] = ffma2(hh, q1.x, acc2[2]);
            acc2[3] = ffma2(hh, q1.y, acc2[3]);
            acc2[4] = ffma2(hh, q2.x, acc2[4]);
            acc2[5] = ffma2(hh, q2.y, acc2[5]);
        }

#pragma unroll
        for (int p = 0; p < 6; p++) {
            const float2 u = upk2(acc2[p]);
            float v0 = u.x, v1 = u.y;
            v0 = (v0 >= 0.f) ? v0 : c_head[5052 + 2 * p] * v0;
            v1 = (v1 >= 0.f) ? v1 : c_head[5053 + 2 * p] * v1;
            out[(2 * p) * 1024 + pix]     = v0;
            out[(2 * p + 1) * 1024 + pix] = v1;
        }
    }
}

// ---------------------------------------------------------------------------
// Kernel 2: four 3x3 convs (12->12, pad1), PReLU(b5_a) after the last.
// Padded 34x34 smem image; f32x2 over oc-pairs, weights [l][ic][tap][oc12].
// ---------------------------------------------------------------------------
__global__ __launch_bounds__(256, 2) void k_body(
    const float* __restrict__ w1, const float* __restrict__ bb1,
    const float* __restrict__ w2, const float* __restrict__ bb2,
    const float* __restrict__ w3, const float* __restrict__ bb3,
    const float* __restrict__ w4, const float* __restrict__ bb4,
    const float* __restrict__ b5a)
{
    extern __shared__ float sm[];
    float* buf = sm;               // 12*1156 = 13872 (34x34 padded)
    float* ws  = sm + 13872;       // 4*1296 = 5184, [l][ic][tap9][oc12]
    float* bs  = sm + 19056;       // 48
    float* a5  = sm + 19104;       // 12

    const int tid = threadIdx.x;
    const int img = blockIdx.x;

    const float* wl[4] = {w1, w2, w3, w4};
    const float* bl[4] = {bb1, bb2, bb3, bb4};
    for (int i = tid; i < 5184; i += 256) {
        const int l = i / 1296;
        const int r = i % 1296;
        const int ic = r / 108;
        const int r2 = r % 108;
        const int t = r2 / 12;
        const int oc = r2 % 12;
        ws[i] = wl[l][(oc * 12 + ic) * 9 + t];
    }
    if (tid < 48) bs[tid] = bl[tid / 12][tid % 12];
    if (tid < 12) a5[tid] = b5a[tid];

    for (int i = tid; i < 13872; i += 256) buf[i] = 0.f;
    __syncthreads();

    const float* src_g = g_h1 + img * 12288;
    for (int i = tid; i < 12288; i += 256) {
        const int c = i >> 10, p = i & 1023;
        const int y = p >> 5, xx = p & 31;
        buf[c * 1156 + (y + 1) * 34 + (xx + 1)] = src_g[i];
    }
    __syncthreads();

    const int x = tid & 31;
    const int y0 = tid >> 5;
    int base[4];
#pragma unroll
    for (int k = 0; k < 4; k++) base[k] = (y0 + 8 * k + 1) * 34 + (x + 1);

    float* gout = g_h5 + img * 12288;

#pragma unroll 1
    for (int l = 0; l < 4; l++) {
        const float* wsl = ws + l * 1296;
        const float* bb = bs + l * 12;

        ull acc2[4][6];
#pragma unroll
        for (int k = 0; k < 4; k++)
#pragma unroll
            for (int p = 0; p < 6; p++) acc2[k][p] = pk2(bb[2 * p], bb[2 * p + 1]);

#pragma unroll 1
        for (int ic = 0; ic < 12; ic++) {
            const float* cb = buf + ic * 1156;
            float n[4][9];
#pragma unroll
            for (int k = 0; k < 4; k++) {
                const float* sp = cb + base[k];
                n[k][0] = sp[-35]; n[k][1] = sp[-34]; n[k][2] = sp[-33];
                n[k][3] = sp[-1];  n[k][4] = sp[0];   n[k][5] = sp[1];
                n[k][6] = sp[33];  n[k][7] = sp[34];  n[k][8] = sp[35];
            }
            const float* wic = wsl + ic * 108;
#pragma unroll
            for (int t = 0; t < 9; t++) {
                const ulonglong2* wt = (const ulonglong2*)(wic + t * 12);
                const ulonglong2 wA = wt[0];
                const ull wC = *(const ull*)(wic + t * 12 + 4);
                const ulonglong2 wB = *(const ulonglong2*)(wic + t * 12 + 6);
#pragma unroll
                for (int k = 0; k < 4; k++) {
                    const ull nb = pk2(n[k][t], n[k][t]);
                    acc2[k][0] = ffma2(nb, wA.x, acc2[k][0]);
                    acc2[k][1] = ffma2(nb, wA.y, acc2[k][1]);
                    acc2[k][2] = ffma2(nb, wC,   acc2[k][2]);
                    acc2[k][3] = ffma2(nb, wB.x, acc2[k][3]);
                    acc2[k][4] = ffma2(nb, wB.y, acc2[k][4]);
                    acc2[k][5] = ffma2(nb, *(const ull*)(wic + t * 12 + 10), acc2[k][5]);
                }
            }
        }

        if (l == 3) {
#pragma unroll
            for (int k = 0; k < 4; k++) {
                const int pix = k * 256 + tid;
#pragma unroll
                for (int p = 0; p < 6; p++) {
                    const float2 u = upk2(acc2[k][p]);
                    float v0 = u.x, v1 = u.y;
                    v0 = (v0 >= 0.f) ? v0 : a5[2 * p] * v0;
                    v1 = (v1 >= 0.f) ? v1 : a5[2 * p + 1] * v1;
                    gout[(2 * p) * 1024 + pix]     = v0;
                    gout[(2 * p + 1) * 1024 + pix] = v1;
                }
            }
        } else {
            __syncthreads();
#pragma unroll
            for (int k = 0; k < 4; k++)
#pragma unroll
                for (int p = 0; p < 6; p++) {
                    const float2 u = upk2(acc2[k][p]);
                    buf[(2 * p) * 1156 + base[k]]     = u.x;
                    buf[(2 * p + 1) * 1156 + base[k]] = u.y;
                }
            __syncthreads();
        }
    }
}

// ---------------------------------------------------------------------------
// Kernel 3 (fused, R10 tail + dc unroll 2): b6 1x1 (12->56) + PReLU in smem,
// then 9x9 stride-2 transposed conv (56->3). Whole image / 512 threads /
// 2 sites per thread; channel chunks of 28; weights staged in smem per chunk.
// ---------------------------------------------------------------------------
__device__ __forceinline__ void cls2(const ulonglong2 ha, const ulonglong2 hb,
                                     const float* wt, int g, ull* P)
{
    const ulonglong2 w0 = *(const ulonglong2*)(wt + g);
    const ulonglong2 w1 = *(const ulonglong2*)(wt + 28 + g);
    const ulonglong2 w2 = *(const ulonglong2*)(wt + 56 + g);
    P[0] = ffma2(ha.x, w0.x, P[0]); P[0] = ffma2(ha.y, w0.y, P[0]);
    P[1] = ffma2(ha.x, w1.x, P[1]); P[1] = ffma2(ha.y, w1.y, P[1]);
    P[2] = ffma2(ha.x, w2.x, P[2]); P[2] = ffma2(ha.y, w2.y, P[2]);
    P[3] = ffma2(hb.x, w0.x, P[3]); P[3] = ffma2(hb.y, w0.y, P[3]);
    P[4] = ffma2(hb.x, w1.x, P[4]); P[4] = ffma2(hb.y, w1.y, P[4]);
    P[5] = ffma2(hb.x, w2.x, P[5]); P[5] = ffma2(hb.y, w2.y, P[5]);
}

__device__ __forceinline__ void accA(const float* hp, const float* wa, ull* A)
{
#pragma unroll
    for (int g = 0; g < 28; g += 4) {
        const ulonglong2 ha = *(const ulonglong2*)(hp + g);
        const ulonglong2 hb = *(const ulonglong2*)(hp + 448 + g);
        cls2(ha, hb, wa, g, A);
    }
}
__device__ __forceinline__ void accB(const float* hp, const float* wa, ull* A,
                                     const float* wb, ull* B)
{
#pragma unroll
    for (int g = 0; g < 28; g += 4) {
        const ulonglong2 ha = *(const ulonglong2*)(hp + g);
        const ulonglong2 hb = *(const ulonglong2*)(hp + 448 + g);
        cls2(ha, hb, wa, g, A);
        cls2(ha, hb, wb, g, B);
    }
}
__device__ __forceinline__ void accD(const float* hp,
                                     const float* w00, ull* A0,
                                     const float* w01, ull* A1,
                                     const float* w10, ull* A2,
                                     const float* w11, ull* A3)
{
#pragma unroll
    for (int g = 0; g < 28; g += 4) {
        const ulonglong2 ha = *(const ulonglong2*)(hp + g);
        const ulonglong2 hb = *(const ulonglong2*)(hp + 448 + g);
        cls2(ha, hb, w00, g, A0);
        cls2(ha, hb, w01, g, A1);
        cls2(ha, hb, w10, g, A2);
        cls2(ha, hb, w11, g, A3);
    }
}

__global__ __launch_bounds__(512, 1) void k_tail(
    const float* __restrict__ b6_w, const float* __restrict__ b6_b,
    const float* __restrict__ b6_a,
    const float* __restrict__ tail_w, const float* __restrict__ tail_b,
    float* __restrict__ out)
{
    extern __shared__ float sm[];
    float* h6c = sm;            // 1296*28 = 36288  [p1296][cl28], tile 36x36
    float* wtc = sm + 36288;    // 81*3*28 = 6804   [tap][oc][cl]
    float* b6w = sm + 43092;    // 672
    float* b6b = sm + 43764;    // 56
    float* b6a = sm + 43820;    // 56
    float* tb  = sm + 43876;    // 4
    // total 43880 floats = 175520 B

    const int tid = threadIdx.x;
    const int img = blockIdx.x;

    const float* h5g = g_h5 + img * 12288;

    for (int i = tid; i < 672; i += 512) b6w[i] = b6_w[i];
    if (tid < 56) { b6b[tid] = b6_b[tid]; b6a[tid] = b6_a[tid]; }
    if (tid < 3) tb[tid] = tail_b[tid];
    __syncthreads();

    const int sy = tid >> 4, sx = tid & 15;   // sites (sy,sx) and (sy,sx+16)

    ull acc[4][6];   // [parity][site0 oc0..2, site1 oc0..2]
#pragma unroll
    for (int p = 0; p < 4; p++)
#pragma unroll
        for (int o = 0; o < 6; o++) acc[p][o] = 0ULL;

#pragma unroll 1
    for (int cc = 0; cc < 2; cc++) {
        const int cb56 = cc * 28;
        if (cc) __syncthreads();    // protect wtc/h6c from previous readers

        // stage tail-weight chunk [tap81][oc3][cl28]
        for (int i = tid; i < 6804; i += 512) {
            const int tap = i / 84;
            const int rest = i % 84;
            const int oc = rest / 28;
            const int cl = rest % 28;
            wtc[i] = tail_w[(cb56 + cl) * 243 + oc * 81 + tap];
        }

        // phase A: expand 12 -> 28 channels for each of up to 3 tile pixels.
#pragma unroll 1
        for (int pp = 0; pp < 3; pp++) {
            const int p = tid + pp * 512;
            if (p >= 1296) break;
            const int r = p / 36, s = p % 36;
            const int iy = r - 2, ix = s - 2;
            const bool valid = (iy >= 0) & (iy < 32) & (ix >= 0) & (ix < 32);
            const float* gp = h5g + iy * 32 + ix;
            float v[12];
#pragma unroll
            for (int c = 0; c < 12; c++)
                v[c] = valid ? __ldg(gp + c * 1024) : 0.f;

            float* hout = h6c + p * 28;
#pragma unroll 1
            for (int cl = 0; cl < 28; cl++) {
                const int c = cb56 + cl;
                const float4* wq = (const float4*)(b6w + c * 12);
                const float4 q0 = wq[0], q1 = wq[1], q2 = wq[2];
                float a = b6b[c];
                a = fmaf(v[0], q0.x, a);  a = fmaf(v[1], q0.y, a);
                a = fmaf(v[2], q0.z, a);  a = fmaf(v[3], q0.w, a);
                a = fmaf(v[4], q1.x, a);  a = fmaf(v[5], q1.y, a);
                a = fmaf(v[6], q1.z, a);  a = fmaf(v[7], q1.w, a);
                a = fmaf(v[8], q2.x, a);  a = fmaf(v[9], q2.y, a);
                a = fmaf(v[10], q2.z, a); a = fmaf(v[11], q2.w, a);
                a = (a >= 0.f) ? a : b6a[c] * a;
                hout[cl] = valid ? a : 0.f;
            }
        }
        __syncthreads();

        // phase B: transposed conv, all 4 parities x 2 sites per thread
        // dr=0 row (ky1 invalid)
        {
            const float* hr = h6c + (sy * 36 + sx) * 28;
            accA(hr, wtc + (8 * 9 + 8) * 84, acc[0]);
#pragma unroll 2
            for (int dc = 1; dc < 5; dc++) {
                const int kx0 = 8 - 2 * dc, kx1 = 9 - 2 * dc;
                accB(hr + dc * 28,
                     wtc + (8 * 9 + kx0) * 84, acc[0],
                     wtc + (8 * 9 + kx1) * 84, acc[1]);
            }
        }
#pragma unroll 1
        for (int dr = 1; dr < 5; dr++) {
            const int ky0 = 8 - 2 * dr, ky1 = 9 - 2 * dr;
            const float* hr = h6c + ((sy + dr) * 36 + sx) * 28;
            accB(hr,
                 wtc + (ky0 * 9 + 8) * 84, acc[0],
                 wtc + (ky1 * 9 + 8) * 84, acc[2]);
#pragma unroll 2
            for (int dc = 1; dc < 5; dc++) {
                const int kx0 = 8 - 2 * dc, kx1 = 9 - 2 * dc;
                accD(hr + dc * 28,
                     wtc + (ky0 * 9 + kx0) * 84, acc[0],
                     wtc + (ky0 * 9 + kx1) * 84, acc[1],
                     wtc + (ky1 * 9 + kx0) * 84, acc[2],
                     wtc + (ky1 * 9 + kx1) * 84, acc[3]);
            }
        }
    }

    float* o = out + img * 3 * 4096;
#pragma unroll
    for (int par = 0; par < 4; par++) {
        const int ry = par >> 1, rx = par & 1;
        const int oy = 2 * sy + ry;
#pragma unroll
        for (int s2 = 0; s2 < 2; s2++) {
            const int ox = 2 * (sx + 16 * s2) + rx;
#pragma unroll
            for (int oc = 0; oc < 3; oc++) {
                const float2 u = upk2(acc[par][s2 * 3 + oc]);
                o[oc * 4096 + oy * 64 + ox] = tb[oc] + (u.x + u.y);
            }
        }
    }
}

// ---------------------------------------------------------------------------
extern "C" void kernel_launch(void* const* d_in, const int* in_sizes, int n_in,
                              void* d_out, int out_size)
{
    const float* x      = (const float*)d_in[0];
    const float* head_w = (const float*)d_in[1];
    const float* head_b = (const float*)d_in[2];
    const float* head_a = (const float*)d_in[3];
    const float* b0_w   = (const float*)d_in[4];
    const float* b0_b   = (const float*)d_in[5];
    const float* b0_a   = (const float*)d_in[6];
    const float* b1_w   = (const float*)d_in[7];
    const float* b1_b   = (const float*)d_in[8];
    const float* b2_w   = (const float*)d_in[9];
    const float* b2_b   = (const float*)d_in[10];
    const float* b3_w   = (const float*)d_in[11];
    const float* b3_b   = (const float*)d_in[12];
    const float* b4_w   = (const float*)d_in[13];
    const float* b4_b   = (const float*)d_in[14];
    const float* b5_a   = (const float*)d_in[15];
    const float* b6_w   = (const float*)d_in[16];
    const float* b6_b   = (const float*)d_in[17];
    const float* b6_a   = (const float*)d_in[18];
    const float* tail_w = (const float*)d_in[19];
    const float* tail_b = (const float*)d_in[20];

    const int SM2 = 19116 * 4;   // k_body dynamic smem (76.5 KB)
    const int SM4 = 43880 * 4;   // k_tail dynamic smem (175.5 KB)
    cudaFuncSetAttribute(k_body, cudaFuncAttributeMaxDynamicSharedMemorySize, SM2);
    cudaFuncSetAttribute(k_tail, cudaFuncAttributeMaxDynamicSharedMemorySize, SM4);

    // stage head weights into constant bank (graph-capturable D2D copy)
    k_prep<<<20, 256>>>(head_w, head_b, head_a, b0_w, b0_b, b0_a);
    void* gsrc = nullptr;  cudaGetSymbolAddress(&gsrc, g_cpack);
    void* cdst = nullptr;  cudaGetSymbolAddress(&cdst, c_head);
    cudaMemcpyAsync(cdst, gsrc, 5064 * sizeof(float), cudaMemcpyDeviceToDevice, 0);

    k_head<<<1024, 256>>>(x);
    k_body<<<1024, 256, SM2>>>(b1_w, b1_b, b2_w, b2_b, b3_w, b3_b, b4_w, b4_b, b5_a);
    k_tail<<<1024, 512, SM4>>>(b6_w, b6_b, b6_a, tail_w, tail_b, (float*)d_out);
}

// round 14
// speedup vs baseline: 1.3171x; 1.0143x over previous
#include <cuda_runtime.h>
#include <cuda_bf16.h>

// FSRCNN: BS=1024, D=56, S=12, H=W=32 -> out 3x64x64
__device__ float g_h1[1024 * 12 * 1024];   // after b0 + prelu
__device__ float g_h5[1024 * 12 * 1024];   // after b4 + prelu(b5_a)
__device__ float g_cpack[5064];            // staging: head constants

// constant-bank image: [0:4256) wh padded [oc][76], [4256:4928) w0t [oc][12],
// [4928:4984) hb, [4984:5040) ha, [5040:5052) b0b, [5052:5064) b0a
__constant__ __align__(16) float c_head[5064];

typedef unsigned long long ull;
__device__ __forceinline__ ull pk2(float lo, float hi) {
    ull r; asm("mov.b64 %0,{%1,%2};" : "=l"(r) : "f"(lo), "f"(hi)); return r;
}
__device__ __forceinline__ float2 upk2(ull v) {
    float2 o; asm("mov.b64 {%0,%1},%2;" : "=f"(o.x), "=f"(o.y) : "l"(v)); return o;
}
__device__ __forceinline__ ull ffma2(ull a, ull b, ull c) {
    ull d; asm("fma.rn.f32x2 %0,%1,%2,%3;" : "=l"(d) : "l"(a), "l"(b), "l"(c)); return d;
}

// ---------------------------------------------------------------------------
// Prep: pack head weights (padded/transposed) into g_cpack for the const copy.
// ---------------------------------------------------------------------------
__global__ __launch_bounds__(256) void k_prep(
    const float* __restrict__ head_w, const float* __restrict__ head_b,
    const float* __restrict__ head_a,
    const float* __restrict__ b0_w, const float* __restrict__ b0_b,
    const float* __restrict__ b0_a)
{
    const int i = blockIdx.x * 256 + threadIdx.x;
    if (i < 4256) {
        const int oc = i / 76, t = i % 76;
        g_cpack[i] = (t < 75) ? head_w[oc * 75 + t] : 0.f;
    } else if (i < 4928) {
        const int j = i - 4256;
        const int oc = j / 12, s = j % 12;
        g_cpack[i] = b0_w[s * 56 + oc];
    } else if (i < 4984) {
        g_cpack[i] = head_b[i - 4928];
    } else if (i < 5040) {
        g_cpack[i] = head_a[i - 4984];
    } else if (i < 5052) {
        g_cpack[i] = b0_b[i - 5040];
    } else if (i < 5064) {
        g_cpack[i] = b0_a[i - 5052];
    }
}

// ---------------------------------------------------------------------------
// Kernel 1: head 5x5 conv (3->56, pad2) + PReLU + b0 1x1 (56->12) + PReLU
// TWO pixels processed jointly per oc pass -> weight LDC traffic halves.
// ---------------------------------------------------------------------------
__global__ __launch_bounds__(256, 1) void k_head(const float* __restrict__ x)
{
    __shared__ float xs[3 * 1024];

    const int tid = threadIdx.x;
    const int img = blockIdx.x;

    const float* xim = x + img * 3072;
    for (int i = tid; i < 3072; i += 256) xs[i] = xim[i];
    __syncthreads();

    float* out = g_h1 + img * 12288;

#pragma unroll 1
    for (int k = 0; k < 2; k++) {
        const int pixA = k * 512 + tid;
        const int pixB = pixA + 256;
        const int yA = pixA >> 5, xA = pixA & 31;
        const int yB = pixB >> 5, xB = pixB & 31;

        // gather both 5x5x3 windows (zero-padded)
        ull xpA[38], xpB[38];
        {
            float xrA[76], xrB[76];
            xrA[75] = 0.f; xrB[75] = 0.f;
#pragma unroll
            for (int ic = 0; ic < 3; ic++)
#pragma unroll
            for (int ky = 0; ky < 5; ky++) {
                const int yyA = yA + ky - 2;
                const int yyB = yB + ky - 2;
#pragma unroll
                for (int kx = 0; kx < 5; kx++) {
                    const int xxA = xA + kx - 2;
                    const int xxB = xB + kx - 2;
                    const bool okA = (yyA >= 0) & (yyA < 32) & (xxA >= 0) & (xxA < 32);
                    const bool okB = (yyB >= 0) & (yyB < 32) & (xxB >= 0) & (xxB < 32);
                    xrA[ic * 25 + ky * 5 + kx] = okA ? xs[ic * 1024 + yyA * 32 + xxA] : 0.f;
                    xrB[ic * 25 + ky * 5 + kx] = okB ? xs[ic * 1024 + yyB * 32 + xxB] : 0.f;
                }
            }
#pragma unroll
            for (int j = 0; j < 38; j++) {
                xpA[j] = pk2(xrA[2 * j], xrA[2 * j + 1]);
                xpB[j] = pk2(xrB[2 * j], xrB[2 * j + 1]);
            }
        }

        ull accA[6], accB[6];
#pragma unroll
        for (int p = 0; p < 6; p++) {
            const ull b = pk2(c_head[5040 + 2 * p], c_head[5041 + 2 * p]);
            accA[p] = b; accB[p] = b;
        }

#pragma unroll 1
        for (int oc = 0; oc < 56; oc++) {
            const ulonglong2* wp = (const ulonglong2*)(c_head + oc * 76);
            ull a0 = 0ULL, a1 = 0ULL, b0 = 0ULL, b1 = 0ULL;
#pragma unroll
            for (int j = 0; j < 19; j++) {
                const ulonglong2 w = wp[j];
                a0 = ffma2(xpA[2 * j],     w.x, a0);
                a1 = ffma2(xpA[2 * j + 1], w.y, a1);
                b0 = ffma2(xpB[2 * j],     w.x, b0);
                b1 = ffma2(xpB[2 * j + 1], w.y, b1);
            }
            const float2 sa0 = upk2(a0), sa1 = upk2(a1);
            const float2 sb0 = upk2(b0), sb1 = upk2(b1);
            const float hbias = c_head[4928 + oc], halpha = c_head[4984 + oc];
            float va = hbias + ((sa0.x + sa0.y) + (sa1.x + sa1.y));
            float vb = hbias + ((sb0.x + sb0.y) + (sb1.x + sb1.y));
            va = (va >= 0.f) ? va : halpha * va;
            vb = (vb >= 0.f) ? vb : halpha * vb;
            const ull ha = pk2(va, va);
            const ull hb = pk2(vb, vb);
            const ulonglong2* q = (const ulonglong2*)(c_head + 4256 + oc * 12);
            const ulonglong2 q0 = q[0], q1 = q[1], q2 = q[2];
            accA[0] = ffma2(ha, q0.x, accA[0]);  accB[0] = ffma2(hb, q0.x, accB[0]);
            accA[1] = ffma2(ha, q0.y, accA[1]);  accB[1] = ffma2(hb, q0.y, accB[1]);
            accA[2] = ffma2(ha, q1.x, accA[2]);  accB[2] = ffma2(hb, q1.x, accB[2]);
            accA[3] = ffma2(ha, q1.y, accA[3]);  accB[3] = ffma2(hb, q1.y, accB[3]);
            accA[4] = ffma2(ha, q2.x, accA[4]);  accB[4] = ffma2(hb, q2.x, accB[4]);
            accA[5] = ffma2(ha, q2.y, accA[5]);  accB[5] = ffma2(hb, q2.y, accB[5]);
        }

#pragma unroll
        for (int p = 0; p < 6; p++) {
            const float2 uA = upk2(accA[p]);
            const float2 uB = upk2(accB[p]);
            const float al0 = c_head[5052 + 2 * p], al1 = c_head[5053 + 2 * p];
            float a0v = uA.x, a1v = uA.y, b0v = uB.x, b1v = uB.y;
            a0v = (a0v >= 0.f) ? a0v : al0 * a0v;
            a1v = (a1v >= 0.f) ? a1v : al1 * a1v;
            b0v = (b0v >= 0.f) ? b0v : al0 * b0v;
            b1v = (b1v >= 0.f) ? b1v : al1 * b1v;
            out[(2 * p) * 1024 + pixA]     = a0v;
            out[(2 * p + 1) * 1024 + pixA] = a1v;
            out[(2 * p) * 1024 + pixB]     = b0v;
            out[(2 * p + 1) * 1024 + pixB] = b1v;
        }
    }
}

// ---------------------------------------------------------------------------
// Kernel 2: four 3x3 convs (12->12, pad1), PReLU(b5_a) after the last.
// Padded 34x34 smem image; f32x2 over oc-pairs, weights [l][ic][tap][oc12].
// ---------------------------------------------------------------------------
__global__ __launch_bounds__(256, 2) void k_body(
    const float* __restrict__ w1, const float* __restrict__ bb1,
    const float* __restrict__ w2, const float* __restrict__ bb2,
    const float* __restrict__ w3, const float* __restrict__ bb3,
    const float* __restrict__ w4, const float* __restrict__ bb4,
    const float* __restrict__ b5a)
{
    extern __shared__ float sm[];
    float* buf = sm;               // 12*1156 = 13872 (34x34 padded)
    float* ws  = sm + 13872;       // 4*1296 = 5184, [l][ic][tap9][oc12]
    float* bs  = sm + 19056;       // 48
    float* a5  = sm + 19104;       // 12

    const int tid = threadIdx.x;
    const int img = blockIdx.x;

    const float* wl[4] = {w1, w2, w3, w4};
    const float* bl[4] = {bb1, bb2, bb3, bb4};
    for (int i = tid; i < 5184; i += 256) {
        const int l = i / 1296;
        const int r = i % 1296;
        const int ic = r / 108;
        const int r2 = r % 108;
        const int t = r2 / 12;
        const int oc = r2 % 12;
        ws[i] = wl[l][(oc * 12 + ic) * 9 + t];
    }
    if (tid < 48) bs[tid] = bl[tid / 12][tid % 12];
    if (tid < 12) a5[tid] = b5a[tid];

    for (int i = tid; i < 13872; i += 256) buf[i] = 0.f;
    __syncthreads();

    const float* src_g = g_h1 + img * 12288;
    for (int i = tid; i < 12288; i += 256) {
        const int c = i >> 10, p = i & 1023;
        const int y = p >> 5, xx = p & 31;
        buf[c * 1156 + (y + 1) * 34 + (xx + 1)] = src_g[i];
    }
    __syncthreads();

    const int x = tid & 31;
    const int y0 = tid >> 5;
    int base[4];
#pragma unroll
    for (int k = 0; k < 4; k++) base[k] = (y0 + 8 * k + 1) * 34 + (x + 1);

    float* gout = g_h5 + img * 12288;

#pragma unroll 1
    for (int l = 0; l < 4; l++) {
        const float* wsl = ws + l * 1296;
        const float* bb = bs + l * 12;

        ull acc2[4][6];
#pragma unroll
        for (int k = 0; k < 4; k++)
#pragma unroll
            for (int p = 0; p < 6; p++) acc2[k][p] = pk2(bb[2 * p], bb[2 * p + 1]);

#pragma unroll 1
        for (int ic = 0; ic < 12; ic++) {
            const float* cb = buf + ic * 1156;
            float n[4][9];
#pragma unroll
            for (int k = 0; k < 4; k++) {
                const float* sp = cb + base[k];
                n[k][0] = sp[-35]; n[k][1] = sp[-34]; n[k][2] = sp[-33];
                n[k][3] = sp[-1];  n[k][4] = sp[0];   n[k][5] = sp[1];
                n[k][6] = sp[33];  n[k][7] = sp[34];  n[k][8] = sp[35];
            }
            const float* wic = wsl + ic * 108;
#pragma unroll
            for (int t = 0; t < 9; t++) {
                const ulonglong2* wt = (const ulonglong2*)(wic + t * 12);
                const ulonglong2 wA = wt[0];
                const ull wC = *(const ull*)(wic + t * 12 + 4);
                const ulonglong2 wB = *(const ulonglong2*)(wic + t * 12 + 6);
#pragma unroll
                for (int k = 0; k < 4; k++) {
                    const ull nb = pk2(n[k][t], n[k][t]);
                    acc2[k][0] = ffma2(nb, wA.x, acc2[k][0]);
                    acc2[k][1] = ffma2(nb, wA.y, acc2[k][1]);
                    acc2[k][2] = ffma2(nb, wC,   acc2[k][2]);
                    acc2[k][3] = ffma2(nb, wB.x, acc2[k][3]);
                    acc2[k][4] = ffma2(nb, wB.y, acc2[k][4]);
                    acc2[k][5] = ffma2(nb, *(const ull*)(wic + t * 12 + 10), acc2[k][5]);
                }
            }
        }

        if (l == 3) {
#pragma unroll
            for (int k = 0; k < 4; k++) {
                const int pix = k * 256 + tid;
#pragma unroll
                for (int p = 0; p < 6; p++) {
                    const float2 u = upk2(acc2[k][p]);
                    float v0 = u.x, v1 = u.y;
                    v0 = (v0 >= 0.f) ? v0 : a5[2 * p] * v0;
                    v1 = (v1 >= 0.f) ? v1 : a5[2 * p + 1] * v1;
                    gout[(2 * p) * 1024 + pix]     = v0;
                    gout[(2 * p + 1) * 1024 + pix] = v1;
                }
            }
        } else {
            __syncthreads();
#pragma unroll
            for (int k = 0; k < 4; k++)
#pragma unroll
                for (int p = 0; p < 6; p++) {
                    const float2 u = upk2(acc2[k][p]);
                    buf[(2 * p) * 1156 + base[k]]     = u.x;
                    buf[(2 * p + 1) * 1156 + base[k]] = u.y;
                }
            __syncthreads();
        }
    }
}

// ---------------------------------------------------------------------------
// Kernel 3 (R13 tail): b6 1x1 (12->56) + PReLU in smem, then 9x9 stride-2
// transposed conv (56->3). Whole image / 512 threads / 2 sites per thread;
// channel chunks of 28; weights staged in smem per chunk; dc loops unroll 2.
// ---------------------------------------------------------------------------
__device__ __forceinline__ void cls2(const ulonglong2 ha, const ulonglong2 hb,
                                     const float* wt, int g, ull* P)
{
    const ulonglong2 w0 = *(const ulonglong2*)(wt + g);
    const ulonglong2 w1 = *(const ulonglong2*)(wt + 28 + g);
    const ulonglong2 w2 = *(const ulonglong2*)(wt + 56 + g);
    P[0] = ffma2(ha.x, w0.x, P[0]); P[0] = ffma2(ha.y, w0.y, P[0]);
    P[1] = ffma2(ha.x, w1.x, P[1]); P[1] = ffma2(ha.y, w1.y, P[1]);
    P[2] = ffma2(ha.x, w2.x, P[2]); P[2] = ffma2(ha.y, w2.y, P[2]);
    P[3] = ffma2(hb.x, w0.x, P[3]); P[3] = ffma2(hb.y, w0.y, P[3]);
    P[4] = ffma2(hb.x, w1.x, P[4]); P[4] = ffma2(hb.y, w1.y, P[4]);
    P[5] = ffma2(hb.x, w2.x, P[5]); P[5] = ffma2(hb.y, w2.y, P[5]);
}

__device__ __forceinline__ void accA(const float* hp, const float* wa, ull* A)
{
#pragma unroll
    for (int g = 0; g < 28; g += 4) {
        const ulonglong2 ha = *(const ulonglong2*)(hp + g);
        const ulonglong2 hb = *(const ulonglong2*)(hp + 448 + g);
        cls2(ha, hb, wa, g, A);
    }
}
__device__ __forceinline__ void accB(const float* hp, const float* wa, ull* A,
                                     const float* wb, ull* B)
{
#pragma unroll
    for (int g = 0; g < 28; g += 4) {
        const ulonglong2 ha = *(const ulonglong2*)(hp + g);
        const ulonglong2 hb = *(const ulonglong2*)(hp + 448 + g);
        cls2(ha, hb, wa, g, A);
        cls2(ha, hb, wb, g, B);
    }
}
__device__ __forceinline__ void accD(const float* hp,
                                     const float* w00, ull* A0,
                                     const float* w01, ull* A1,
                                     const float* w10, ull* A2,
                                     const float* w11, ull* A3)
{
#pragma unroll
    for (int g = 0; g < 28; g += 4) {
        const ulonglong2 ha = *(const ulonglong2*)(hp + g);
        const ulonglong2 hb = *(const ulonglong2*)(hp + 448 + g);
        cls2(ha, hb, w00, g, A0);
        cls2(ha, hb, w01, g, A1);
        cls2(ha, hb, w10, g, A2);
        cls2(ha, hb, w11, g, A3);
    }
}

__global__ __launch_bounds__(512, 1) void k_tail(
    const float* __restrict__ b6_w, const float* __restrict__ b6_b,
    const float* __restrict__ b6_a,
    const float* __restrict__ tail_w, const float* __restrict__ tail_b,
    float* __restrict__ out)
{
    extern __shared__ float sm[];
    float* h6c = sm;            // 1296*28 = 36288  [p1296][cl28], tile 36x36
    float* wtc = sm + 36288;    // 81*3*28 = 6804   [tap][oc][cl]
    float* b6w = sm + 43092;    // 672
    float* b6b = sm + 43764;    // 56
    float* b6a = sm + 43820;    // 56
    float* tb  = sm + 43876;    // 4
    // total 43880 floats = 175520 B

    const int tid = threadIdx.x;
    const int img = blockIdx.x;

    const float* h5g = g_h5 + img * 12288;

    for (int i = tid; i < 672; i += 512) b6w[i] = b6_w[i];
    if (tid < 56) { b6b[tid] = b6_b[tid]; b6a[tid] = b6_a[tid]; }
    if (tid < 3) tb[tid] = tail_b[tid];
    __syncthreads();

    const int sy = tid >> 4, sx = tid & 15;   // sites (sy,sx) and (sy,sx+16)

    ull acc[4][6];   // [parity][site0 oc0..2, site1 oc0..2]
#pragma unroll
    for (int p = 0; p < 4; p++)
#pragma unroll
        for (int o = 0; o < 6; o++) acc[p][o] = 0ULL;

#pragma unroll 1
    for (int cc = 0; cc < 2; cc++) {
        const int cb56 = cc * 28;
        if (cc) __syncthreads();    // protect wtc/h6c from previous readers

        // stage tail-weight chunk [tap81][oc3][cl28]
        for (int i = tid; i < 6804; i += 512) {
            const int tap = i / 84;
            const int rest = i % 84;
            const int oc = rest / 28;
            const int cl = rest % 28;
            wtc[i] = tail_w[(cb56 + cl) * 243 + oc * 81 + tap];
        }

        // phase A: expand 12 -> 28 channels for each of up to 3 tile pixels.
#pragma unroll 1
        for (int pp = 0; pp < 3; pp++) {
            const int p = tid + pp * 512;
            if (p >= 1296) break;
            const int r = p / 36, s = p % 36;
            const int iy = r - 2, ix = s - 2;
            const bool valid = (iy >= 0) & (iy < 32) & (ix >= 0) & (ix < 32);
            const float* gp = h5g + iy * 32 + ix;
            float v[12];
#pragma unroll
            for (int c = 0; c < 12; c++)
                v[c] = valid ? __ldg(gp + c * 1024) : 0.f;

            float* hout = h6c + p * 28;
#pragma unroll 1
            for (int cl = 0; cl < 28; cl++) {
                const int c = cb56 + cl;
                const float4* wq = (const float4*)(b6w + c * 12);
                const float4 q0 = wq[0], q1 = wq[1], q2 = wq[2];
                float a = b6b[c];
                a = fmaf(v[0], q0.x, a);  a = fmaf(v[1], q0.y, a);
                a = fmaf(v[2], q0.z, a);  a = fmaf(v[3], q0.w, a);
                a = fmaf(v[4], q1.x, a);  a = fmaf(v[5], q1.y, a);
                a = fmaf(v[6], q1.z, a);  a = fmaf(v[7], q1.w, a);
                a = fmaf(v[8], q2.x, a);  a = fmaf(v[9], q2.y, a);
                a = fmaf(v[10], q2.z, a); a = fmaf(v[11], q2.w, a);
                a = (a >= 0.f) ? a : b6a[c] * a;
                hout[cl] = valid ? a : 0.f;
            }
        }
        __syncthreads();

        // phase B: transposed conv, all 4 parities x 2 sites per thread
        // dr=0 row (ky1 invalid)
        {
            const float* hr = h6c + (sy * 36 + sx) * 28;
            accA(hr, wtc + (8 * 9 + 8) * 84, acc[0]);
#pragma unroll 2
            for (int dc = 1; dc < 5; dc++) {
                const int kx0 = 8 - 2 * dc, kx1 = 9 - 2 * dc;
                accB(hr + dc * 28,
                     wtc + (8 * 9 + kx0) * 84, acc[0],
                     wtc + (8 * 9 + kx1) * 84, acc[1]);
            }
        }
#pragma unroll 1
        for (int dr = 1; dr < 5; dr++) {
            const int ky0 = 8 - 2 * dr, ky1 = 9 - 2 * dr;
            const float* hr = h6c + ((sy + dr) * 36 + sx) * 28;
            accB(hr,
                 wtc + (ky0 * 9 + 8) * 84, acc[0],
                 wtc + (ky1 * 9 + 8) * 84, acc[2]);
#pragma unroll 2
            for (int dc = 1; dc < 5; dc++) {
                const int kx0 = 8 - 2 * dc, kx1 = 9 - 2 * dc;
                accD(hr + dc * 28,
                     wtc + (ky0 * 9 + kx0) * 84, acc[0],
                     wtc + (ky0 * 9 + kx1) * 84, acc[1],
                     wtc + (ky1 * 9 + kx0) * 84, acc[2],
                     wtc + (ky1 * 9 + kx1) * 84, acc[3]);
            }
        }
    }

    float* o = out + img * 3 * 4096;
#pragma unroll
    for (int par = 0; par < 4; par++) {
        const int ry = par >> 1, rx = par & 1;
        const int oy = 2 * sy + ry;
#pragma unroll
        for (int s2 = 0; s2 < 2; s2++) {
            const int ox = 2 * (sx + 16 * s2) + rx;
#pragma unroll
            for (int oc = 0; oc < 3; oc++) {
                const float2 u = upk2(acc[par][s2 * 3 + oc]);
                o[oc * 4096 + oy * 64 + ox] = tb[oc] + (u.x + u.y);
            }
        }
    }
}

// ---------------------------------------------------------------------------
extern "C" void kernel_launch(void* const* d_in, const int* in_sizes, int n_in,
                              void* d_out, int out_size)
{
    const float* x      = (const float*)d_in[0];
    const float* head_w = (const float*)d_in[1];
    const float* head_b = (const float*)d_in[2];
    const float* head_a = (const float*)d_in[3];
    const float* b0_w   = (const float*)d_in[4];
    const float* b0_b   = (const float*)d_in[5];
    const float* b0_a   = (const float*)d_in[6];
    const float* b1_w   = (const float*)d_in[7];
    const float* b1_b   = (const float*)d_in[8];
    const float* b2_w   = (const float*)d_in[9];
    const float* b2_b   = (const float*)d_in[10];
    const float* b3_w   = (const float*)d_in[11];
    const float* b3_b   = (const float*)d_in[12];
    const float* b4_w   = (const float*)d_in[13];
    const float* b4_b   = (const float*)d_in[14];
    const float* b5_a   = (const float*)d_in[15];
    const float* b6_w   = (const float*)d_in[16];
    const float* b6_b   = (const float*)d_in[17];
    const float* b6_a   = (const float*)d_in[18];
    const float* tail_w = (const float*)d_in[19];
    const float* tail_b = (const float*)d_in[20];

    const int SM2 = 19116 * 4;   // k_body dynamic smem (76.5 KB)
    const int SM4 = 43880 * 4;   // k_tail dynamic smem (175.5 KB)
    cudaFuncSetAttribute(k_body, cudaFuncAttributeMaxDynamicSharedMemorySize, SM2);
    cudaFuncSetAttribute(k_tail, cudaFuncAttributeMaxDynamicSharedMemorySize, SM4);

    // stage head weights into constant bank (graph-capturable D2D copy)
    k_prep<<<20, 256>>>(head_w, head_b, head_a, b0_w, b0_b, b0_a);
    void* gsrc = nullptr;  cudaGetSymbolAddress(&gsrc, g_cpack);
    void* cdst = nullptr;  cudaGetSymbolAddress(&cdst, c_head);
    cudaMemcpyAsync(cdst, gsrc, 5064 * sizeof(float), cudaMemcpyDeviceToDevice, 0);

    k_head<<<1024, 256>>>(x);
    k_body<<<1024, 256, SM2>>>(b1_w, b1_b, b2_w, b2_b, b3_w, b3_b, b4_w, b4_b, b5_a);
    k_tail<<<1024, 512, SM4>>>(b6_w, b6_b, b6_a, tail_w, tail_b, (float*)d_out);
}